// round 8
// baseline (speedup 1.0000x reference)
#include <cuda_runtime.h>
#include <cstddef>

#define NN 16384
#define CC 10000
#define DD 128
#define LR 0.5f

#define NVEC   (CC / 4)       // 2500 float4 per label row
#define SCANT  64             // threads per block (2 warps)
#define CHUNKV (SCANT * 2)    // 128 float4 = 2KB lockstep chunks

#define EPI_TOT     2000      // last-2000 ticket holders run the epilogue
#define CLS_PER_EPI 5         // 2000 * 5 = 10000 classes
#define F4_PER_EPI  (CLS_PER_EPI * DD / 4)   // 160 float4 per slice

// Scratch (no cudaMalloc allowed). Zero-initialized at load; the epilogue
// re-zeroes everything so each graph replay starts clean.
__device__ float g_sum[CC * DD];
__device__ float g_cnt[CC];
__device__ int   g_done = 0;   // completed scan blocks
__device__ int   g_fin  = 0;   // completed epilogue slices

// ---------------------------------------------------------------------------
// One 64-thread block per sample.
// Phase 1: lockstep early-exit scan of the one-hot row in 2KB chunks
//          (MLP=2 per thread, ONE barrier per chunk; s_cls is written at most
//          once ever, and any value read from it is THE correct class, so the
//          write/read race across adjacent chunks is benign).
// Phase 2: red-atomics of preds[n,:] into g_sum[class,:], count into g_cnt.
// Phase 3: ticket via g_done. The last EPI_TOT ticket holders spin until all
//          scan work is globally visible, then finalize a 5-class slice:
//            out = (1 - LR*cnt/(cnt+1))*center + (LR/(cnt+1))*sum
//          and re-zero their slice of g_sum/g_cnt. Last epilogue finisher
//          resets the counters (safe: every spinner already exited its spin
//          before incrementing g_fin).
// ---------------------------------------------------------------------------
__global__ void __launch_bounds__(SCANT) cl_fused_kernel(
    const float* __restrict__ labels,   // [N, C]
    const float* __restrict__ preds,    // [N, D]
    const float* __restrict__ center,   // [C, D]
    float* __restrict__ out)            // [C, D]
{
    __shared__ int s_cls;
    __shared__ int s_epi;
    const int n = blockIdx.x;
    const int t = threadIdx.x;

    if (t == 0) s_cls = -1;
    __syncthreads();

    // ---- Phase 1: scan ----
    const float4* __restrict__ row =
        reinterpret_cast<const float4*>(labels + (size_t)n * CC);

    int cls = -1;
    #pragma unroll 1
    for (int base = 0; base < NVEC; base += CHUNKV) {
        const int i0 = base + t;
        const int i1 = base + t + SCANT;
        float4 v0, v1;
        const bool p0 = (i0 < NVEC);
        const bool p1 = (i1 < NVEC);
        if (p0) v0 = __ldg(&row[i0]);
        if (p1) v1 = __ldg(&row[i1]);

        int found = -1;
        if (p0) {
            if (v0.x != 0.0f)      found = 4 * i0 + 0;
            else if (v0.y != 0.0f) found = 4 * i0 + 1;
            else if (v0.z != 0.0f) found = 4 * i0 + 2;
            else if (v0.w != 0.0f) found = 4 * i0 + 3;
        }
        if (found < 0 && p1) {
            if (v1.x != 0.0f)      found = 4 * i1 + 0;
            else if (v1.y != 0.0f) found = 4 * i1 + 1;
            else if (v1.z != 0.0f) found = 4 * i1 + 2;
            else if (v1.w != 0.0f) found = 4 * i1 + 3;
        }

        if (found >= 0) s_cls = found;   // at most one write, ever
        __syncthreads();                 // lockstep + visibility
        cls = s_cls;
        if (cls >= 0) break;
    }

    // ---- Phase 2: accumulate ----
    const float* __restrict__ pr = preds + (size_t)n * DD;
    atomicAdd(&g_sum[(size_t)cls * DD + t],         __ldg(&pr[t]));
    atomicAdd(&g_sum[(size_t)cls * DD + t + SCANT], __ldg(&pr[t + SCANT]));
    if (t == 0) atomicAdd(&g_cnt[cls], 1.0f);

    // Make this block's REDs globally visible before taking a ticket.
    __threadfence();
    __syncthreads();

    // ---- Phase 3: ticket + epilogue ----
    if (t == 0) {
        const int old  = atomicAdd(&g_done, 1);
        const int eidx = old - (NN - EPI_TOT);
        if (eidx >= 0) {
            // Spin until every scan block's fence+increment has landed.
            while (*(volatile int*)&g_done != NN) { __nanosleep(100); }
        }
        s_epi = eidx;
    }
    __syncthreads();
    const int eidx = s_epi;
    if (eidx < 0) return;

    __threadfence();   // acquire: order spin-observation before scratch reads

    const int base4 = eidx * F4_PER_EPI;
    const float4* __restrict__ gs = reinterpret_cast<const float4*>(g_sum);
    const float4* __restrict__ gc = reinterpret_cast<const float4*>(center);
    float4* __restrict__ po  = reinterpret_cast<float4*>(out);
    float4* __restrict__ gsw = reinterpret_cast<float4*>(g_sum);

    #pragma unroll 1
    for (int j = t; j < F4_PER_EPI; j += SCANT) {
        const int i4 = base4 + j;
        const int c  = i4 >> 5;                     // 32 float4 per class

        const float cnt = __ldcg(&g_cnt[c]);        // L2-coherent read
        const float4 s  = __ldcg(&gs[i4]);
        const float4 ce = __ldg(&gc[i4]);

        const float inv = 1.0f / (cnt + 1.0f);
        const float a   = 1.0f - LR * cnt * inv;    // coeff on center
        const float b   = LR * inv;                 // coeff on sum

        float4 r;
        r.x = a * ce.x + b * s.x;
        r.y = a * ce.y + b * s.y;
        r.z = a * ce.z + b * s.z;
        r.w = a * ce.w + b * s.w;
        po[i4]  = r;
        gsw[i4] = make_float4(0.f, 0.f, 0.f, 0.f);  // clean for next replay
    }

    __syncthreads();                                // cnt reads done
    if (t < CLS_PER_EPI) {
        g_cnt[eidx * CLS_PER_EPI + t] = 0.0f;       // slice-private classes
    }
    __threadfence();
    __syncthreads();
    if (t == 0) {
        const int f = atomicAdd(&g_fin, 1);
        if (f == EPI_TOT - 1) {                     // last epilogue finisher
            g_done = 0;                             // all spins already exited
            g_fin  = 0;
        }
    }
}

// ---------------------------------------------------------------------------
// Launch. Inputs per metadata: embeded_preds [N*D], labels [N*C],
// center [C*D]. Output: updated_center [C*D] float32.
// ---------------------------------------------------------------------------
extern "C" void kernel_launch(void* const* d_in, const int* in_sizes, int n_in,
                              void* d_out, int out_size) {
    const float* preds  = (const float*)d_in[0];
    const float* labels = (const float*)d_in[1];
    const float* center = (const float*)d_in[2];
    float* out = (float*)d_out;

    (void)in_sizes; (void)n_in; (void)out_size;

    cl_fused_kernel<<<NN, SCANT>>>(labels, preds, center, out);
}

// round 11
// speedup vs baseline: 1.0245x; 1.0245x over previous
#include <cuda_runtime.h>
#include <cstddef>

#define NN 16384
#define CC 10000
#define DD 128
#define LR 0.5f

#define NVEC  (CC / 4)   // 2500 float4 per label row
#define SCANT 64         // threads per scan block (2 warps)
                         // chunk = 64 float4 = 1KB

// Scratch (no cudaMalloc allowed). Zero-initialized at module load; the
// finalize kernel re-zeroes after each use so every graph replay starts clean.
__device__ float g_sum[CC * DD];  // per-class sum of preds
__device__ float g_cnt[CC];      // per-class sample count

// ---------------------------------------------------------------------------
// Kernel 1: one 64-thread block per sample. Lockstep early-exit scan in 1KB
// chunks (1 float4 per thread per chunk, ONE barrier per chunk). s_cls is
// written at most once in the block's lifetime and the write always precedes
// the barrier that every reader crosses, so a single barrier gives uniform
// visibility. E[bytes/row] ~ (40KB + 1KB)/2 = 20.5KB (floor: 20KB).
// Then red-atomics of preds[n,:] into the class accumulators.
// ---------------------------------------------------------------------------
__global__ void __launch_bounds__(SCANT) cl_scan_accum_kernel(
    const float* __restrict__ labels,   // [N, C]
    const float* __restrict__ preds)    // [N, D]
{
    __shared__ int s_cls;
    const int n = blockIdx.x;
    const int t = threadIdx.x;

    if (t == 0) s_cls = -1;
    __syncthreads();

    const float4* __restrict__ row =
        reinterpret_cast<const float4*>(labels + (size_t)n * CC);

    int cls = -1;
    #pragma unroll 1
    for (int base = 0; base < NVEC; base += SCANT) {
        const int i = base + t;
        float4 v;
        const bool p = (i < NVEC);
        if (p) v = __ldg(&row[i]);

        int found = -1;
        if (p) {
            if (v.x != 0.0f)      found = 4 * i + 0;
            else if (v.y != 0.0f) found = 4 * i + 1;
            else if (v.z != 0.0f) found = 4 * i + 2;
            else if (v.w != 0.0f) found = 4 * i + 3;
        }

        if (found >= 0) s_cls = found;   // at most one write, ever
        __syncthreads();                 // write visible to ALL before read
        cls = s_cls;                     // uniform value across the block
        if (cls >= 0) break;             // uniform branch
    }

    // Accumulate preds[n,:] into g_sum[cls,:]; 64 threads x 2 dims.
    const float* __restrict__ pr = preds + (size_t)n * DD;
    atomicAdd(&g_sum[(size_t)cls * DD + t],         __ldg(&pr[t]));
    atomicAdd(&g_sum[(size_t)cls * DD + t + SCANT], __ldg(&pr[t + SCANT]));
    if (t == 0) atomicAdd(&g_cnt[cls], 1.0f);
}

// ---------------------------------------------------------------------------
// Kernel 2: finalize (float4 + 2x ILP) + re-zero scratch. Launched with
// Programmatic Dependent Launch: prefetch the scan-independent center values
// into registers BEFORE cudaGridDependencySynchronize(), overlapping the
// center DRAM traffic and launch ramp with the scan kernel's tail.
//   out[c] = (1 - LR*cnt/(cnt+1)) * center[c] + (LR/(cnt+1)) * sum[c]
// Thread handles float4 pair {2i, 2i+1} (same class: 32 float4 per class).
// A 256-thread block covers 16 whole classes -> g_cnt block-private:
// read before the barrier, zero after it. Scratch reads use __ldcg (L2) so
// the scan's L2 red-atomics are seen coherently.
// ---------------------------------------------------------------------------
__global__ void __launch_bounds__(256) cl_finalize_kernel(
    const float* __restrict__ center,   // [C, D]
    float* __restrict__ out)            // [C, D]
{
    const int i  = blockIdx.x * 256 + threadIdx.x;
    const int i4 = 2 * i;                       // first float4 index
    const int c  = i4 >> 5;                     // 32 float4 per class

    const float4* __restrict__ gc = reinterpret_cast<const float4*>(center);

    // Pre-dependency work: center does not depend on the scan kernel.
    const float4 c0 = __ldg(&gc[i4]);
    const float4 c1 = __ldg(&gc[i4 + 1]);

    cudaGridDependencySynchronize();            // wait for scan completion

    const float4* __restrict__ gs = reinterpret_cast<const float4*>(g_sum);
    const float cnt = __ldcg(&g_cnt[c]);
    const float4 s0 = __ldcg(&gs[i4]);
    const float4 s1 = __ldcg(&gs[i4 + 1]);

    const float inv = 1.0f / (cnt + 1.0f);
    const float a   = 1.0f - LR * cnt * inv;    // coeff on center
    const float b   = LR * inv;                 // coeff on sum

    float4 r0, r1;
    r0.x = a * c0.x + b * s0.x;  r0.y = a * c0.y + b * s0.y;
    r0.z = a * c0.z + b * s0.z;  r0.w = a * c0.w + b * s0.w;
    r1.x = a * c1.x + b * s1.x;  r1.y = a * c1.y + b * s1.y;
    r1.z = a * c1.z + b * s1.z;  r1.w = a * c1.w + b * s1.w;

    float4* __restrict__ po = reinterpret_cast<float4*>(out);
    po[i4]     = r0;
    po[i4 + 1] = r1;

    float4* gsw = reinterpret_cast<float4*>(g_sum);
    const float4 z = make_float4(0.f, 0.f, 0.f, 0.f);
    gsw[i4]     = z;                            // clean for next replay
    gsw[i4 + 1] = z;

    __syncthreads();                            // all g_cnt reads done
    if ((i & 15) == 0) {                        // one thread per class
        g_cnt[c] = 0.0f;
    }
}

// ---------------------------------------------------------------------------
// Launch. Inputs per metadata: embeded_preds [N*D], labels [N*C],
// center [C*D]. Output: updated_center [C*D] float32.
// Finalize is launched via cudaLaunchKernelEx with the PDL attribute so its
// prologue overlaps the scan kernel's tail (graph-capturable per CUDA 12+).
// ---------------------------------------------------------------------------
extern "C" void kernel_launch(void* const* d_in, const int* in_sizes, int n_in,
                              void* d_out, int out_size) {
    const float* preds  = (const float*)d_in[0];
    const float* labels = (const float*)d_in[1];
    const float* center = (const float*)d_in[2];
    float* out = (float*)d_out;

    (void)in_sizes; (void)n_in; (void)out_size;

    cl_scan_accum_kernel<<<NN, SCANT>>>(labels, preds);

    cudaLaunchConfig_t cfg = {};
    cfg.gridDim  = dim3((CC * DD / 8) / 256);   // 625 blocks
    cfg.blockDim = dim3(256);
    cfg.dynamicSmemBytes = 0;
    cfg.stream = 0;                             // same (legacy) stream

    cudaLaunchAttribute attr[1];
    attr[0].id = cudaLaunchAttributeProgrammaticStreamSerialization;
    attr[0].val.programmaticStreamSerializationAllowed = 1;
    cfg.attrs = attr;
    cfg.numAttrs = 1;

    cudaLaunchKernelEx(&cfg, cl_finalize_kernel, center, out);
}